// round 1
// baseline (speedup 1.0000x reference)
#include <cuda_runtime.h>

#define NNODES 3000
#define BATCH  16
#define FEAT   43
#define NREL   3
#define NBUCKET (NREL*NNODES)
#define GBN    8   // nodes per block in RGCN kernel

// ---------------- scratch (static __device__, no allocation) ----------------
__device__ float d_x [BATCH*NNODES*FEAT];   // temporal features
__device__ float d_h1[BATCH*NNODES*FEAT];   // after RGCN layer 1
__device__ float d_h2[BATCH*NNODES*FEAT];   // after RGCN layer 2
__device__ int   dc_cnt[NBUCKET];
__device__ int   dc_off[NBUCKET+1];
__device__ int   dc_cur[NBUCKET];
__device__ float dc_inv[NBUCKET];
__device__ int   dc_src[96000];

// ---------------- CSR build ----------------
__global__ void k_zero() {
    int i = blockIdx.x*blockDim.x + threadIdx.x;
    if (i < NBUCKET) dc_cnt[i] = 0;
}

__global__ void k_count(const int* __restrict__ ei, const int* __restrict__ et, int E) {
    int e = blockIdx.x*blockDim.x + threadIdx.x;
    if (e >= E) return;
    atomicAdd(&dc_cnt[et[e]*NNODES + ei[E+e]], 1);
}

__global__ void k_scan(int E) {
    __shared__ int ss[1024];
    int tid = threadIdx.x;
    int c[9]; int s = 0;
    #pragma unroll
    for (int i = 0; i < 9; i++) {
        int g = tid*9 + i;
        c[i] = (g < NBUCKET) ? dc_cnt[g] : 0;
        s += c[i];
    }
    ss[tid] = s;
    __syncthreads();
    for (int d = 1; d < 1024; d <<= 1) {
        int v = (tid >= d) ? ss[tid-d] : 0;
        __syncthreads();
        ss[tid] += v;
        __syncthreads();
    }
    int run = ss[tid] - s;   // exclusive prefix of this thread's chunk
    #pragma unroll
    for (int i = 0; i < 9; i++) {
        int g = tid*9 + i;
        if (g < NBUCKET) {
            dc_off[g] = run;
            dc_cur[g] = run;
            dc_inv[g] = 1.0f / (float)(c[i] > 1 ? c[i] : 1);
            run += c[i];
        }
    }
    if (tid == 0) dc_off[NBUCKET] = E;
}

__global__ void k_fill(const int* __restrict__ ei, const int* __restrict__ et, int E) {
    int e = blockIdx.x*blockDim.x + threadIdx.x;
    if (e >= E) return;
    int g = et[e]*NNODES + ei[E+e];
    int p = atomicAdd(&dc_cur[g], 1);
    dc_src[p] = ei[e];
}

// ---------------- temporal feature extraction ----------------
// thread per (b,n); writes d_x[(b*N+n)*43 + f]: f 0..19 short, 20..39 mid, 40..42 long
__global__ void k_temporal(const float* __restrict__ obs,
    const float* __restrict__ ws1, const float* __restrict__ bs1,
    const float* __restrict__ ws2, const float* __restrict__ bs2,
    const float* __restrict__ wm1, const float* __restrict__ bm1,
    const float* __restrict__ wm2, const float* __restrict__ bm2)
{
    __shared__ float s_ws1[27],  s_bs1[3],  s_ws2[2880], s_bs2[20];
    __shared__ float s_wm1[189], s_bm1[3],  s_wm2[1800], s_bm2[20];
    int tid = threadIdx.x;
    for (int i = tid; i < 27;   i += 128) s_ws1[i] = ws1[i];
    for (int i = tid; i < 2880; i += 128) s_ws2[i] = ws2[i];
    for (int i = tid; i < 189;  i += 128) s_wm1[i] = wm1[i];
    for (int i = tid; i < 1800; i += 128) s_wm2[i] = wm2[i];
    if (tid < 3)  { s_bs1[tid] = bs1[tid]; s_bm1[tid] = bm1[tid]; }
    if (tid < 20) { s_bs2[tid] = bs2[tid]; s_bm2[tid] = bm2[tid]; }
    __syncthreads();

    int idx = blockIdx.x*128 + tid;           // 48000 = 375*128 exact
    int b = idx / NNODES, n = idx % NNODES;
    const float* base = obs + ((size_t)(b*3)*NNODES + n)*50;

    float ob[3][50];
    #pragma unroll
    for (int c = 0; c < 3; c++) {
        const float* p = base + (size_t)c*NNODES*50;
        for (int t = 0; t < 50; t++) ob[c][t] = __ldg(p + t);
    }

    float* xo = d_x + (size_t)(b*NNODES + n)*FEAT;

    // long path: relu(max over T)
    #pragma unroll
    for (int c = 0; c < 3; c++) {
        float m = ob[c][0];
        for (int t = 1; t < 50; t++) m = fmaxf(m, ob[c][t]);
        xo[40 + c] = fmaxf(m, 0.f);
    }

    // short path: conv(1x3,3->3)+relu then conv(1x48,3->20)+relu
    {
        float acc[20];
        #pragma unroll
        for (int o = 0; o < 20; o++) acc[o] = s_bs2[o];
        for (int t = 0; t < 48; t++) {
            float w0[3], w1[3], w2[3];
            #pragma unroll
            for (int ci = 0; ci < 3; ci++) { w0[ci]=ob[ci][t]; w1[ci]=ob[ci][t+1]; w2[ci]=ob[ci][t+2]; }
            float s1[3];
            #pragma unroll
            for (int co = 0; co < 3; co++) {
                float v = s_bs1[co];
                #pragma unroll
                for (int ci = 0; ci < 3; ci++) {
                    v += w0[ci]*s_ws1[(co*3+ci)*3+0];
                    v += w1[ci]*s_ws1[(co*3+ci)*3+1];
                    v += w2[ci]*s_ws1[(co*3+ci)*3+2];
                }
                s1[co] = fmaxf(v, 0.f);
            }
            #pragma unroll
            for (int o = 0; o < 20; o++)
                acc[o] += s1[0]*s_ws2[(o*3+0)*48+t] + s1[1]*s_ws2[(o*3+1)*48+t] + s1[2]*s_ws2[(o*3+2)*48+t];
        }
        #pragma unroll
        for (int o = 0; o < 20; o++) xo[o] = fmaxf(acc[o], 0.f);
    }

    // mid path: conv(1x21,3->3)+relu then conv(1x30,3->20)+relu
    {
        float acc[20];
        #pragma unroll
        for (int o = 0; o < 20; o++) acc[o] = s_bm2[o];
        for (int t = 0; t < 30; t++) {
            float m1[3] = { s_bm1[0], s_bm1[1], s_bm1[2] };
            for (int ci = 0; ci < 3; ci++) {
                for (int k = 0; k < 21; k++) {
                    float ov = ob[ci][t+k];
                    #pragma unroll
                    for (int co = 0; co < 3; co++) m1[co] += ov*s_wm1[(co*3+ci)*21+k];
                }
            }
            #pragma unroll
            for (int co = 0; co < 3; co++) m1[co] = fmaxf(m1[co], 0.f);
            #pragma unroll
            for (int o = 0; o < 20; o++)
                acc[o] += m1[0]*s_wm2[(o*3+0)*30+t] + m1[1]*s_wm2[(o*3+1)*30+t] + m1[2]*s_wm2[(o*3+2)*30+t];
        }
        #pragma unroll
        for (int o = 0; o < 20; o++) xo[20+o] = fmaxf(acc[o], 0.f);
    }
}

// ---------------- RGCN layer (aggregate-then-transform) ----------------
// out[b,n,:] = leaky( bias + x[b,n]@root + sum_r ((sum_{src in N_r(n)} x[b,src]) * inv_cnt_r[n]) @ rel_r )
__global__ void k_rgcn(int layer,
                       const float* __restrict__ root,
                       const float* __restrict__ rel,
                       const float* __restrict__ bias)
{
    extern __shared__ float sm[];
    float* w_s    = sm;              // 4*1849: [root, rel0, rel1, rel2], row-major [f][o]
    float* bias_s = sm + 7396;       // 43
    float* agg_s  = sm + 7439;       // [r][b][nl][f] = 3*16*GBN*43

    const float* xin  = (layer == 0) ? d_x  : d_h1;
    float*       xout = (layer == 0) ? d_h1 : d_h2;

    int tid = threadIdx.x;
    for (int i = tid; i < 1849;   i += 128) w_s[i]       = __ldg(root + i);
    for (int i = tid; i < 3*1849; i += 128) w_s[1849+i]  = __ldg(rel + i);
    if (tid < FEAT) bias_s[tid] = bias[tid];

    // gather slots: thread owns (b,f) pairs idx = tid + j*128, idx < 688
    int bj[6], fj[6]; bool vj[6];
    #pragma unroll
    for (int j = 0; j < 6; j++) {
        int idx = tid + j*128;
        vj[j] = idx < BATCH*FEAT;
        int ii = vj[j] ? idx : 0;
        bj[j] = ii / FEAT; fj[j] = ii - bj[j]*FEAT;
    }

    int node0 = blockIdx.x * GBN;
    for (int nl = 0; nl < GBN; nl++) {
        int n = node0 + nl;
        #pragma unroll
        for (int r = 0; r < NREL; r++) {
            int s_ = dc_off[r*NNODES + n], e_ = dc_off[r*NNODES + n + 1];
            float a[6] = {0,0,0,0,0,0};
            for (int e = s_; e < e_; e++) {
                int src = __ldg(&dc_src[e]);
                #pragma unroll
                for (int j = 0; j < 6; j++)
                    if (vj[j]) a[j] += __ldg(&xin[(size_t)(bj[j]*NNODES + src)*FEAT + fj[j]]);
            }
            float inv = dc_inv[r*NNODES + n];
            #pragma unroll
            for (int j = 0; j < 6; j++)
                if (vj[j]) agg_s[((r*BATCH + bj[j])*GBN + nl)*FEAT + fj[j]] = a[j]*inv;
        }
    }
    __syncthreads();

    // matmul phase: thread -> (b, nl), 16*8 = 128
    int b  = tid & 15;
    int nl = tid >> 4;
    int n  = node0 + nl;

    float outv[FEAT];
    #pragma unroll
    for (int o = 0; o < FEAT; o++) outv[o] = bias_s[o];

    const float* xr = xin + (size_t)(b*NNODES + n)*FEAT;
    for (int f = 0; f < FEAT; f++) {
        float xv = __ldg(xr + f);
        const float* wr = w_s + f*FEAT;
        #pragma unroll
        for (int o = 0; o < FEAT; o++) outv[o] += xv * wr[o];   // broadcast LDS
    }
    #pragma unroll
    for (int r = 0; r < NREL; r++) {
        const float* ar = agg_s + ((r*BATCH + b)*GBN + nl)*FEAT;
        const float* wb = w_s + (1 + r)*1849;
        for (int f = 0; f < FEAT; f++) {
            float av = ar[f];
            const float* wr = wb + f*FEAT;
            #pragma unroll
            for (int o = 0; o < FEAT; o++) outv[o] += av * wr[o];
        }
    }

    float* yo = xout + (size_t)(b*NNODES + n)*FEAT;
    #pragma unroll
    for (int o = 0; o < FEAT; o++) {
        float v = outv[o];
        yo[o] = v > 0.f ? v : 0.01f*v;     // leaky_relu 0.01
    }
}

// ---------------- head: select + 1x1 conv(87->1) + softmax over 501 ----------------
__global__ void k_head(const float* __restrict__ la, const int* __restrict__ sel,
                       const float* __restrict__ wf, const float* __restrict__ bf,
                       float* __restrict__ out)
{
    __shared__ float sh[501];
    __shared__ float rbuf[16];
    int b = blockIdx.x, t = threadIdx.x;
    if (t == 0) sh[0] = 0.f;                 // cash logit
    if (t < 500) {
        int node = __ldg(&sel[t]);
        float v = __ldg(bf) + __ldg(wf)*__ldg(&la[b*501 + 1 + t]);
        const float* xr = d_x  + (size_t)(b*NNODES + node)*FEAT;
        const float* hr = d_h2 + (size_t)(b*NNODES + node)*FEAT;
        #pragma unroll
        for (int f = 0; f < FEAT; f++) v += __ldg(&wf[1 + f])  * __ldg(xr + f);
        #pragma unroll
        for (int f = 0; f < FEAT; f++) v += __ldg(&wf[44 + f]) * __ldg(hr + f);
        sh[1 + t] = v;
    }
    __syncthreads();

    float m = -1e30f;
    for (int i = t; i < 501; i += 512) m = fmaxf(m, sh[i]);
    #pragma unroll
    for (int off = 16; off; off >>= 1) m = fmaxf(m, __shfl_xor_sync(0xffffffffu, m, off));
    if ((t & 31) == 0) rbuf[t >> 5] = m;
    __syncthreads();
    if (t == 0) { float mm = rbuf[0]; for (int w = 1; w < 16; w++) mm = fmaxf(mm, rbuf[w]); rbuf[0] = mm; }
    __syncthreads();
    float gm = rbuf[0];
    __syncthreads();

    float ssum = 0.f;
    for (int i = t; i < 501; i += 512) { float e = __expf(sh[i] - gm); sh[i] = e; ssum += e; }
    #pragma unroll
    for (int off = 16; off; off >>= 1) ssum += __shfl_xor_sync(0xffffffffu, ssum, off);
    if ((t & 31) == 0) rbuf[t >> 5] = ssum;
    __syncthreads();
    if (t == 0) { float s2 = 0.f; for (int w = 0; w < 16; w++) s2 += rbuf[w]; rbuf[0] = s2; }
    __syncthreads();
    float invs = 1.0f / rbuf[0];
    for (int i = t; i < 501; i += 512) out[b*501 + i] = sh[i] * invs;
}

// ---------------- launch ----------------
extern "C" void kernel_launch(void* const* d_in, const int* in_sizes, int n_in,
                              void* d_out, int out_size)
{
    const float* obs   = (const float*)d_in[0];
    const float* la    = (const float*)d_in[1];
    const int*   ei    = (const int*)  d_in[2];
    const int*   et    = (const int*)  d_in[3];
    const int*   sel   = (const int*)  d_in[4];
    const float* ws1   = (const float*)d_in[5];
    const float* bs1   = (const float*)d_in[6];
    const float* ws2   = (const float*)d_in[7];
    const float* bs2   = (const float*)d_in[8];
    const float* wm1   = (const float*)d_in[9];
    const float* bm1   = (const float*)d_in[10];
    const float* wm2   = (const float*)d_in[11];
    const float* bm2   = (const float*)d_in[12];
    const float* root1 = (const float*)d_in[13];
    const float* rel1  = (const float*)d_in[14];
    const float* bias1 = (const float*)d_in[15];
    const float* root2 = (const float*)d_in[16];
    const float* rel2  = (const float*)d_in[17];
    const float* bias2 = (const float*)d_in[18];
    const float* wf    = (const float*)d_in[19];
    const float* bf    = (const float*)d_in[20];
    float* out = (float*)d_out;

    int E = in_sizes[3];   // 96000

    // CSR build (deterministic structure; within-bucket order from atomics, fp-safe)
    k_zero <<<(NBUCKET + 255)/256, 256>>>();
    k_count<<<(E + 255)/256,       256>>>(ei, et, E);
    k_scan <<<1, 1024>>>(E);
    k_fill <<<(E + 255)/256,       256>>>(ei, et, E);

    // temporal features -> d_x
    k_temporal<<<(BATCH*NNODES)/128, 128>>>(obs, ws1, bs1, ws2, bs2, wm1, bm1, wm2, bm2);

    // RGCN layers
    int smem = (7396 + 43 + 3*BATCH*GBN*FEAT) * (int)sizeof(float);   // ~93.6 KB
    cudaFuncSetAttribute(k_rgcn, cudaFuncAttributeMaxDynamicSharedMemorySize, smem);
    k_rgcn<<<NNODES/GBN, 128, smem>>>(0, root1, rel1, bias1);
    k_rgcn<<<NNODES/GBN, 128, smem>>>(1, root2, rel2, bias2);

    // head
    k_head<<<BATCH, 512>>>(la, sel, wf, bf, out);
}

// round 5
// speedup vs baseline: 1.6742x; 1.6742x over previous
#include <cuda_runtime.h>

#define NNODES 3000
#define BATCH  16
#define FEAT   43
#define NREL   3
#define NBUCKET (NREL*NNODES)
#define ROWS   (BATCH*NNODES)     // 48000
#define GBN    8                  // nodes per block in RGCN kernel (round-1 value)
#define OBSTR  129                // padded stride for obs staging (bank-conflict free)

// ---------------- scratch (static __device__, no allocation) ----------------
__device__ float d_x [BATCH*NNODES*FEAT];   // temporal features
__device__ float d_h1[BATCH*NNODES*FEAT];   // after RGCN layer 1
__device__ float d_h2[BATCH*NNODES*FEAT];   // after RGCN layer 2
__device__ int   dc_cnt[NBUCKET];
__device__ int   dc_off[NBUCKET+1];
__device__ int   dc_cur[NBUCKET];
__device__ float dc_inv[NBUCKET];
__device__ int   dc_src[96000];

// ---------------- CSR build (round-1 verbatim) ----------------
__global__ void k_zero() {
    int i = blockIdx.x*blockDim.x + threadIdx.x;
    if (i < NBUCKET) dc_cnt[i] = 0;
}

__global__ void k_count(const int* __restrict__ ei, const int* __restrict__ et, int E) {
    int e = blockIdx.x*blockDim.x + threadIdx.x;
    if (e >= E) return;
    atomicAdd(&dc_cnt[et[e]*NNODES + ei[E+e]], 1);
}

__global__ void k_scan(int E) {
    __shared__ int ss[1024];
    int tid = threadIdx.x;
    int c[9]; int s = 0;
    #pragma unroll
    for (int i = 0; i < 9; i++) {
        int g = tid*9 + i;
        c[i] = (g < NBUCKET) ? dc_cnt[g] : 0;
        s += c[i];
    }
    ss[tid] = s;
    __syncthreads();
    for (int d = 1; d < 1024; d <<= 1) {
        int v = (tid >= d) ? ss[tid-d] : 0;
        __syncthreads();
        ss[tid] += v;
        __syncthreads();
    }
    int run = ss[tid] - s;   // exclusive prefix of this thread's chunk
    #pragma unroll
    for (int i = 0; i < 9; i++) {
        int g = tid*9 + i;
        if (g < NBUCKET) {
            dc_off[g] = run;
            dc_cur[g] = run;
            dc_inv[g] = 1.0f / (float)(c[i] > 1 ? c[i] : 1);
            run += c[i];
        }
    }
    if (tid == 0) dc_off[NBUCKET] = E;
}

__global__ void k_fill(const int* __restrict__ ei, const int* __restrict__ et, int E) {
    int e = blockIdx.x*blockDim.x + threadIdx.x;
    if (e >= E) return;
    int g = et[e]*NNODES + ei[E+e];
    int p = atomicAdd(&dc_cur[g], 1);
    dc_src[p] = ei[e];
}

// ---------------- temporal feature extraction (staged shared version) ----------------
// 128 threads, thread per (b,n). obs staged in shared, layout [c*50+t][slot]
// with row stride OBSTR=129: staging writes AND compute reads conflict-free.
__global__ void __launch_bounds__(128) k_temporal(const float* __restrict__ obs,
    const float* __restrict__ ws1, const float* __restrict__ bs1,
    const float* __restrict__ ws2, const float* __restrict__ bs2,
    const float* __restrict__ wm1, const float* __restrict__ bm1,
    const float* __restrict__ wm2, const float* __restrict__ bm2)
{
    extern __shared__ float sm[];
    float* s_ob   = sm;                 // 150*129 = 19350
    float* s_ws2t = sm + 19350;         // 2880  [t][c][o]
    float* s_wm2t = sm + 19350 + 2880;  // 1800  [t][c][o]
    float* s_wm1  = s_wm2t + 1800;      // 189
    float* s_ws1  = s_wm1  + 189;       // 27
    float* s_bs1  = s_ws1  + 27;        // 3
    float* s_bm1  = s_bs1  + 3;         // 3
    float* s_bs2  = s_bm1  + 3;         // 20
    float* s_bm2  = s_bs2  + 20;        // 20
    int tid = threadIdx.x;

    for (int i = tid; i < 2880; i += 128) {
        int o = i/144, c = (i/48)%3, t = i%48;        // ws2 (20,3,1,48)
        s_ws2t[(t*3+c)*20 + o] = __ldg(&ws2[i]);
    }
    for (int i = tid; i < 1800; i += 128) {
        int o = i/90, c = (i/30)%3, t = i%30;         // wm2 (20,3,1,30)
        s_wm2t[(t*3+c)*20 + o] = __ldg(&wm2[i]);
    }
    for (int i = tid; i < 189; i += 128) s_wm1[i] = __ldg(&wm1[i]);
    if (tid < 27) s_ws1[tid] = __ldg(&ws1[tid]);
    if (tid < 3)  { s_bs1[tid] = __ldg(&bs1[tid]); s_bm1[tid] = __ldg(&bm1[tid]); }
    if (tid < 20) { s_bs2[tid] = __ldg(&bs2[tid]); s_bm2[tid] = __ldg(&bm2[tid]); }

    int idx0 = blockIdx.x*128;
    // cooperative coalesced obs load: element i -> (slot, c, t)
    for (int i = tid; i < 128*150; i += 128) {
        int slot = i/150, rem = i%150, c = rem/50, t = rem%50;
        int g = idx0 + slot; int b = g/NNODES, n = g%NNODES;
        s_ob[(c*50+t)*OBSTR + slot] = __ldg(&obs[(((size_t)(b*3+c))*NNODES + n)*50 + t]);
    }
    __syncthreads();

    const float* myob = s_ob + tid;
    float* xo = d_x + (size_t)(idx0 + tid)*FEAT;

    // ---- long path: relu(max over T) ----
    for (int c = 0; c < 3; c++) {
        float m = myob[(c*50)*OBSTR];
        for (int t = 1; t < 50; t++) m = fmaxf(m, myob[(c*50+t)*OBSTR]);
        xo[40+c] = fmaxf(m, 0.f);
    }

    // ---- short path: conv(1x3,3->3)+relu -> conv(1x48,3->20)+relu ----
    {
        float acc[20];
        #pragma unroll
        for (int o = 0; o < 20; o++) acc[o] = s_bs2[o];
        float x0[3], x1[3];
        #pragma unroll
        for (int c = 0; c < 3; c++) { x0[c] = myob[(c*50+0)*OBSTR]; x1[c] = myob[(c*50+1)*OBSTR]; }
        for (int t = 0; t < 48; t++) {
            float x2[3];
            #pragma unroll
            for (int c = 0; c < 3; c++) x2[c] = myob[(c*50+t+2)*OBSTR];
            float s1[3];
            #pragma unroll
            for (int co = 0; co < 3; co++) {
                float v = s_bs1[co];
                #pragma unroll
                for (int ci = 0; ci < 3; ci++)
                    v += x0[ci]*s_ws1[(co*3+ci)*3+0] + x1[ci]*s_ws1[(co*3+ci)*3+1] + x2[ci]*s_ws1[(co*3+ci)*3+2];
                s1[co] = fmaxf(v, 0.f);
            }
            const float* wt = s_ws2t + t*60;
            #pragma unroll
            for (int c = 0; c < 3; c++) {
                float v = s1[c];
                const float* w = wt + c*20;
                #pragma unroll
                for (int o = 0; o < 20; o++) acc[o] += v*w[o];
            }
            #pragma unroll
            for (int c = 0; c < 3; c++) { x0[c] = x1[c]; x1[c] = x2[c]; }
        }
        #pragma unroll
        for (int o = 0; o < 20; o++) xo[o] = fmaxf(acc[o], 0.f);
    }

    // ---- mid path: conv(1x21,3->3)+relu -> conv(1x30,3->20)+relu ----
    // two passes of 15 output positions to keep register arrays small
    {
        float accm[20];
        #pragma unroll
        for (int o = 0; o < 20; o++) accm[o] = s_bm2[o];
        for (int pass = 0; pass < 2; pass++) {
            float m1[3][15];
            #pragma unroll
            for (int co = 0; co < 3; co++)
                #pragma unroll
                for (int tt = 0; tt < 15; tt++) m1[co][tt] = s_bm1[co];
            for (int ci = 0; ci < 3; ci++) {
                for (int k = 0; k < 21; k++) {
                    float w0 = s_wm1[(0*3+ci)*21+k];
                    float w1 = s_wm1[(1*3+ci)*21+k];
                    float w2 = s_wm1[(2*3+ci)*21+k];
                    const float* pb = myob + (ci*50 + pass*15 + k)*OBSTR;
                    #pragma unroll
                    for (int tt = 0; tt < 15; tt++) {
                        float ov = pb[tt*OBSTR];
                        m1[0][tt] += ov*w0; m1[1][tt] += ov*w1; m1[2][tt] += ov*w2;
                    }
                }
            }
            #pragma unroll
            for (int tt = 0; tt < 15; tt++) {
                const float* wt = s_wm2t + (pass*15+tt)*60;
                #pragma unroll
                for (int c = 0; c < 3; c++) {
                    float v = fmaxf(m1[c][tt], 0.f);
                    const float* w = wt + c*20;
                    #pragma unroll
                    for (int o = 0; o < 20; o++) accm[o] += v*w[o];
                }
            }
        }
        #pragma unroll
        for (int o = 0; o < 20; o++) xo[20+o] = fmaxf(accm[o], 0.f);
    }
}

// ---------------- RGCN layer (round-1 verbatim, fused aggregate+transform) ----------------
__global__ void k_rgcn(int layer,
                       const float* __restrict__ root,
                       const float* __restrict__ rel,
                       const float* __restrict__ bias)
{
    extern __shared__ float sm[];
    float* w_s    = sm;              // 4*1849: [root, rel0, rel1, rel2], row-major [f][o]
    float* bias_s = sm + 7396;       // 43
    float* agg_s  = sm + 7439;       // [r][b][nl][f] = 3*16*GBN*43

    const float* xin  = (layer == 0) ? d_x  : d_h1;
    float*       xout = (layer == 0) ? d_h1 : d_h2;

    int tid = threadIdx.x;
    for (int i = tid; i < 1849;   i += 128) w_s[i]       = __ldg(root + i);
    for (int i = tid; i < 3*1849; i += 128) w_s[1849+i]  = __ldg(rel + i);
    if (tid < FEAT) bias_s[tid] = bias[tid];

    // gather slots: thread owns (b,f) pairs idx = tid + j*128, idx < 688
    int bj[6], fj[6]; bool vj[6];
    #pragma unroll
    for (int j = 0; j < 6; j++) {
        int idx = tid + j*128;
        vj[j] = idx < BATCH*FEAT;
        int ii = vj[j] ? idx : 0;
        bj[j] = ii / FEAT; fj[j] = ii - bj[j]*FEAT;
    }

    int node0 = blockIdx.x * GBN;
    for (int nl = 0; nl < GBN; nl++) {
        int n = node0 + nl;
        #pragma unroll
        for (int r = 0; r < NREL; r++) {
            int s_ = dc_off[r*NNODES + n], e_ = dc_off[r*NNODES + n + 1];
            float a[6] = {0,0,0,0,0,0};
            for (int e = s_; e < e_; e++) {
                int src = __ldg(&dc_src[e]);
                #pragma unroll
                for (int j = 0; j < 6; j++)
                    if (vj[j]) a[j] += __ldg(&xin[(size_t)(bj[j]*NNODES + src)*FEAT + fj[j]]);
            }
            float inv = dc_inv[r*NNODES + n];
            #pragma unroll
            for (int j = 0; j < 6; j++)
                if (vj[j]) agg_s[((r*BATCH + bj[j])*GBN + nl)*FEAT + fj[j]] = a[j]*inv;
        }
    }
    __syncthreads();

    // matmul phase: thread -> (b, nl), 16*8 = 128
    int b  = tid & 15;
    int nl = tid >> 4;
    int n  = node0 + nl;

    float outv[FEAT];
    #pragma unroll
    for (int o = 0; o < FEAT; o++) outv[o] = bias_s[o];

    const float* xr = xin + (size_t)(b*NNODES + n)*FEAT;
    for (int f = 0; f < FEAT; f++) {
        float xv = __ldg(xr + f);
        const float* wr = w_s + f*FEAT;
        #pragma unroll
        for (int o = 0; o < FEAT; o++) outv[o] += xv * wr[o];   // broadcast LDS
    }
    #pragma unroll
    for (int r = 0; r < NREL; r++) {
        const float* ar = agg_s + ((r*BATCH + b)*GBN + nl)*FEAT;
        const float* wb = w_s + (1 + r)*1849;
        for (int f = 0; f < FEAT; f++) {
            float av = ar[f];
            const float* wr = wb + f*FEAT;
            #pragma unroll
            for (int o = 0; o < FEAT; o++) outv[o] += av * wr[o];
        }
    }

    float* yo = xout + (size_t)(b*NNODES + n)*FEAT;
    #pragma unroll
    for (int o = 0; o < FEAT; o++) {
        float v = outv[o];
        yo[o] = v > 0.f ? v : 0.01f*v;     // leaky_relu 0.01
    }
}

// ---------------- head: select + 1x1 conv(87->1) + softmax over 501 (round-1 verbatim) ----------------
__global__ void k_head(const float* __restrict__ la, const int* __restrict__ sel,
                       const float* __restrict__ wf, const float* __restrict__ bf,
                       float* __restrict__ out)
{
    __shared__ float sh[501];
    __shared__ float rbuf[16];
    int b = blockIdx.x, t = threadIdx.x;
    if (t == 0) sh[0] = 0.f;                 // cash logit
    if (t < 500) {
        int node = __ldg(&sel[t]);
        float v = __ldg(bf) + __ldg(wf)*__ldg(&la[b*501 + 1 + t]);
        const float* xr = d_x  + (size_t)(b*NNODES + node)*FEAT;
        const float* hr = d_h2 + (size_t)(b*NNODES + node)*FEAT;
        #pragma unroll
        for (int f = 0; f < FEAT; f++) v += __ldg(&wf[1 + f])  * __ldg(xr + f);
        #pragma unroll
        for (int f = 0; f < FEAT; f++) v += __ldg(&wf[44 + f]) * __ldg(hr + f);
        sh[1 + t] = v;
    }
    __syncthreads();

    float m = -1e30f;
    for (int i = t; i < 501; i += 512) m = fmaxf(m, sh[i]);
    #pragma unroll
    for (int off = 16; off; off >>= 1) m = fmaxf(m, __shfl_xor_sync(0xffffffffu, m, off));
    if ((t & 31) == 0) rbuf[t >> 5] = m;
    __syncthreads();
    if (t == 0) { float mm = rbuf[0]; for (int w = 1; w < 16; w++) mm = fmaxf(mm, rbuf[w]); rbuf[0] = mm; }
    __syncthreads();
    float gm = rbuf[0];
    __syncthreads();

    float ssum = 0.f;
    for (int i = t; i < 501; i += 512) { float e = __expf(sh[i] - gm); sh[i] = e; ssum += e; }
    #pragma unroll
    for (int off = 16; off; off >>= 1) ssum += __shfl_xor_sync(0xffffffffu, ssum, off);
    if ((t & 31) == 0) rbuf[t >> 5] = ssum;
    __syncthreads();
    if (t == 0) { float s2 = 0.f; for (int w = 0; w < 16; w++) s2 += rbuf[w]; rbuf[0] = s2; }
    __syncthreads();
    float invs = 1.0f / rbuf[0];
    for (int i = t; i < 501; i += 512) out[b*501 + i] = sh[i] * invs;
}

// ---------------- launch ----------------
extern "C" void kernel_launch(void* const* d_in, const int* in_sizes, int n_in,
                              void* d_out, int out_size)
{
    const float* obs   = (const float*)d_in[0];
    const float* la    = (const float*)d_in[1];
    const int*   ei    = (const int*)  d_in[2];
    const int*   et    = (const int*)  d_in[3];
    const int*   sel   = (const int*)  d_in[4];
    const float* ws1   = (const float*)d_in[5];
    const float* bs1   = (const float*)d_in[6];
    const float* ws2   = (const float*)d_in[7];
    const float* bs2   = (const float*)d_in[8];
    const float* wm1   = (const float*)d_in[9];
    const float* bm1   = (const float*)d_in[10];
    const float* wm2   = (const float*)d_in[11];
    const float* bm2   = (const float*)d_in[12];
    const float* root1 = (const float*)d_in[13];
    const float* rel1  = (const float*)d_in[14];
    const float* bias1 = (const float*)d_in[15];
    const float* root2 = (const float*)d_in[16];
    const float* rel2  = (const float*)d_in[17];
    const float* bias2 = (const float*)d_in[18];
    const float* wf    = (const float*)d_in[19];
    const float* bf    = (const float*)d_in[20];
    float* out = (float*)d_out;

    int E = in_sizes[3];   // 96000

    // CSR build (deterministic structure; within-bucket order from atomics, fp-safe)
    k_zero <<<(NBUCKET + 255)/256, 256>>>();
    k_count<<<(E + 255)/256,       256>>>(ei, et, E);
    k_scan <<<1, 1024>>>(E);
    k_fill <<<(E + 255)/256,       256>>>(ei, et, E);

    // temporal features -> d_x  (staged shared-memory version)
    int smem_t = (150*OBSTR + 2880 + 1800 + 189 + 27 + 3 + 3 + 20 + 20) * (int)sizeof(float);
    cudaFuncSetAttribute(k_temporal, cudaFuncAttributeMaxDynamicSharedMemorySize, smem_t);
    k_temporal<<<ROWS/128, 128, smem_t>>>(obs, ws1, bs1, ws2, bs2, wm1, bm1, wm2, bm2);

    // RGCN layers (round-1 verbatim)
    int smem = (7396 + 43 + 3*BATCH*GBN*FEAT) * (int)sizeof(float);   // ~93.6 KB
    cudaFuncSetAttribute(k_rgcn, cudaFuncAttributeMaxDynamicSharedMemorySize, smem);
    k_rgcn<<<NNODES/GBN, 128, smem>>>(0, root1, rel1, bias1);
    k_rgcn<<<NNODES/GBN, 128, smem>>>(1, root2, rel2, bias2);

    // head
    k_head<<<BATCH, 512>>>(la, sel, wf, bf, out);
}